// round 2
// baseline (speedup 1.0000x reference)
#include <cuda_runtime.h>

// VolumeRenderer: B=4, HW=65536, N=48
// inputs: rgb (B,HW,N,3) f32, sigma (B,HW,N,1) f32, z_vals (B,HW,N) f32
// outputs: rgb_map (B,HW,3) then depth_map (B,HW), concatenated in d_out.

#define TOTAL_RAYS (4 * 65536)      // 262144
#define NSAMP      48
#define RAYS_PB    256              // rays (= threads) per block
#define CHUNK      8                // samples staged per chunk
#define NCHUNKS    (NSAMP / CHUNK)  // 6
#define RP         257              // padded ray pitch in smem (conflict control)

__global__ __launch_bounds__(RAYS_PB)
void volrend_kernel(const float* __restrict__ rgb,
                    const float* __restrict__ sigma,
                    const float* __restrict__ z_vals,
                    float* __restrict__ out)
{
    // Transposed staging: [element][ray]. Reads in compute phase are
    // lane==consecutive-ray -> conflict-free. Stores are <=2-way (RP=257).
    __shared__ float rgb_s[3 * CHUNK][RP];  // 24 rows
    __shared__ float sig_s[CHUNK][RP];
    __shared__ float z_s[CHUNK][RP];

    const int tid   = threadIdx.x;
    const int ray0  = blockIdx.x * RAYS_PB;
    const int ray_g = ray0 + tid;

    // Scan carry state. Phantom "previous sample" with sigma=0 contributes
    // weight 0 and multiplies T by (1+1e-10) once -> negligible vs 1e-3 tol.
    float T = 1.0f;
    float acc_r = 0.f, acc_g = 0.f, acc_b = 0.f, acc_d = 0.f;
    float z_p = 0.f, s_p = 0.f, r_p = 0.f, g_p = 0.f, b_p = 0.f;

    for (int c = 0; c < NCHUNKS; ++c) {
        // ---- coalesced global loads into registers (overlap w/ prior compute)
        float4 rv[6];
#pragma unroll
        for (int i = 0; i < 6; ++i) {
            int f = tid + RAYS_PB * i;          // 0..1535 float4s of rgb tile
            int ray = f / 6;                    // 6 float4 = 24 floats per ray
            int j   = f % 6;
            rv[i] = *reinterpret_cast<const float4*>(
                rgb + (size_t)(ray0 + ray) * (NSAMP * 3) + c * (CHUNK * 3) + 4 * j);
        }
        float4 sv[2], zv[2];
#pragma unroll
        for (int i = 0; i < 2; ++i) {
            int f = tid + RAYS_PB * i;          // 0..511 float4s
            int ray = f / 2;                    // 2 float4 = 8 floats per ray
            int j   = f % 2;
            size_t base = (size_t)(ray0 + ray) * NSAMP + c * CHUNK + 4 * j;
            sv[i] = *reinterpret_cast<const float4*>(sigma + base);
            zv[i] = *reinterpret_cast<const float4*>(z_vals + base);
        }

        __syncthreads();   // prior chunk's compute must be done before overwrite

        // ---- transpose into smem
#pragma unroll
        for (int i = 0; i < 6; ++i) {
            int f = tid + RAYS_PB * i;
            int ray = f / 6;
            int e   = 4 * (f % 6);
            rgb_s[e + 0][ray] = rv[i].x;
            rgb_s[e + 1][ray] = rv[i].y;
            rgb_s[e + 2][ray] = rv[i].z;
            rgb_s[e + 3][ray] = rv[i].w;
        }
#pragma unroll
        for (int i = 0; i < 2; ++i) {
            int f = tid + RAYS_PB * i;
            int ray = f / 2;
            int e   = 4 * (f % 2);
            sig_s[e + 0][ray] = sv[i].x;
            sig_s[e + 1][ray] = sv[i].y;
            sig_s[e + 2][ray] = sv[i].z;
            sig_s[e + 3][ray] = sv[i].w;
            z_s[e + 0][ray] = zv[i].x;
            z_s[e + 1][ray] = zv[i].y;
            z_s[e + 2][ray] = zv[i].z;
            z_s[e + 3][ray] = zv[i].w;
        }

        __syncthreads();

        // ---- per-thread sequential scan over this chunk (lag-by-one)
#pragma unroll
        for (int j = 0; j < CHUNK; ++j) {
            float zc = z_s[j][tid];
            float sc = sig_s[j][tid];
            float rc = rgb_s[3 * j + 0][tid];
            float gc = rgb_s[3 * j + 1][tid];
            float bc = rgb_s[3 * j + 2][tid];

            // finalize previous sample now that its dist is known
            float dist = zc - z_p;
            float e    = __expf(-s_p * dist);
            float w    = T * (1.0f - e);
            acc_r += w * r_p;
            acc_g += w * g_p;
            acc_b += w * b_p;
            acc_d += w * z_p;
            T *= (e + 1e-10f);

            z_p = zc; s_p = sc; r_p = rc; g_p = gc; b_p = bc;
        }
    }

    // ---- final sample: dist capped at 1e10
    {
        float e = __expf(-s_p * 1e10f);
        float w = T * (1.0f - e);
        acc_r += w * r_p;
        acc_g += w * g_p;
        acc_b += w * b_p;
        acc_d += w * z_p;
    }

    out[(size_t)ray_g * 3 + 0] = acc_r;
    out[(size_t)ray_g * 3 + 1] = acc_g;
    out[(size_t)ray_g * 3 + 2] = acc_b;
    out[(size_t)TOTAL_RAYS * 3 + ray_g] = acc_d;
}

extern "C" void kernel_launch(void* const* d_in, const int* in_sizes, int n_in,
                              void* d_out, int out_size)
{
    const float* rgb    = (const float*)d_in[0];
    const float* sigma  = (const float*)d_in[1];
    const float* z_vals = (const float*)d_in[2];
    float* out = (float*)d_out;

    dim3 grid(TOTAL_RAYS / RAYS_PB);   // 1024 blocks
    dim3 block(RAYS_PB);               // 256 threads
    volrend_kernel<<<grid, block>>>(rgb, sigma, z_vals, out);
}